// round 14
// baseline (speedup 1.0000x reference)
#include <cuda_runtime.h>
#include <cuda_bf16.h>
#include <cstdint>
#include <cstddef>

// ---------------- problem dims ----------------
static constexpr int Mdim = 8192;   // B*T
static constexpr int Ndim = 1024;   // codebook rows
static constexpr int Kdim = 512;    // D

// ---------------- tiling: 64x128 CTA, B via smem, A via LDG fragments -----
static constexpr int MT = 64;
static constexpr int NT = 128;
static constexpr int KC = 64;            // K elems per chunk (64 bf16 = 128B rows)
static constexpr int NCHUNK = Kdim / KC; // 8
static constexpr int THREADS = 128;      // 4 warps: 2 (M) x 2 (N), 32x64 each
static constexpr int NKB = Kdim / 16;    // 32 k16 blocks
static constexpr int NMB = Mdim / 16;    // 512 m16 blocks
static constexpr int STAGE_BYTES = 16384;             // B only: 128 rows x 128B
static constexpr int SM_TOTAL = 64 * 132 * 4;         // max(2 stages 32K, epi 33.8K)

__device__ float g_xsq[Mdim];
__device__ float g_csq[Ndim];
__device__ uint4 g_af[(size_t)NMB * NKB * 32];        // A frag records, 8 MB
__device__ __nv_bfloat16 g_cb[(size_t)Ndim * Kdim];   // B bf16 rows, 1 MB

// ---------------- helpers ----------------
__device__ __forceinline__ uint32_t smem_u32(const void* p) {
    uint32_t a;
    asm("{ .reg .u64 t; cvta.to.shared.u64 t, %1; cvt.u32.u64 %0, t; }"
        : "=r"(a) : "l"(p));
    return a;
}
#define SW128(o) ((o) ^ (((o) >> 3) & 0x70))

__device__ __forceinline__ uint32_t pack_bf16x2(float a, float b) {
    uint32_t r;
    asm("cvt.rn.bf16x2.f32 %0, %1, %2;" : "=r"(r) : "f"(b), "f"(a));
    return r;
}
__device__ __forceinline__ void cp16(uint32_t dst, const void* src) {
    asm volatile("cp.async.cg.shared.global [%0], [%1], 16;"
                 :: "r"(dst), "l"(src) : "memory");
}
#define CP_COMMIT() asm volatile("cp.async.commit_group;" ::: "memory")
#define CP_WAIT(n)  asm volatile("cp.async.wait_group %0;" :: "n"(n) : "memory")

__device__ __forceinline__ void ldsm_x4(uint32_t* r, uint32_t addr) {
    asm volatile("ldmatrix.sync.aligned.m8n8.x4.shared.b16 {%0,%1,%2,%3}, [%4];"
                 : "=r"(r[0]), "=r"(r[1]), "=r"(r[2]), "=r"(r[3]) : "r"(addr));
}
__device__ __forceinline__ void mma_bf16(float* c, const uint32_t* a,
                                         uint32_t b0, uint32_t b1) {
    asm volatile(
        "mma.sync.aligned.m16n8k16.row.col.f32.bf16.bf16.f32 "
        "{%0,%1,%2,%3}, {%4,%5,%6,%7}, {%8,%9}, {%0,%1,%2,%3};"
        : "+f"(c[0]), "+f"(c[1]), "+f"(c[2]), "+f"(c[3])
        : "r"(a[0]), "r"(a[1]), "r"(a[2]), "r"(a[3]), "r"(b0), "r"(b1));
}

// ------- fused prep, one read pass --------------------------------------
// Warps [0, NMB): A 16-row block -> frag record (R10-proven layout) + norms.
//   A record lane l: x=M[r][k] y=M[r+8][k] z=M[r][k+8] w=M[r+8][k+8],
//   r = blk*16+(l>>2), k = kb*16+(l&3)*2.
// Warps [NMB, NMB+Ndim): one codebook row -> bf16 row (R5-proven) + norm.
__global__ void __launch_bounds__(256) prep_kernel(const float* __restrict__ x,
                                                   const float* __restrict__ cb) {
    int wid  = blockIdx.x * 8 + (threadIdx.x >> 5);
    int lane = threadIdx.x & 31;
    if (wid < NMB) {
        const int blk = wid;
        const int r0 = blk * 16 + (lane >> 2);
        const int c0 = (lane & 3) * 2;
        const float* row0 = x + (size_t)r0 * Kdim;
        const float* row1 = row0 + (size_t)8 * Kdim;
        uint4* dst = g_af + (size_t)blk * NKB * 32;
        float s0 = 0.f, s1 = 0.f;
        #pragma unroll 4
        for (int kb = 0; kb < NKB; kb++) {
            const int c = kb * 16 + c0;
            float2 a00 = *reinterpret_cast<const float2*>(row0 + c);
            float2 a01 = *reinterpret_cast<const float2*>(row0 + c + 8);
            float2 a10 = *reinterpret_cast<const float2*>(row1 + c);
            float2 a11 = *reinterpret_cast<const float2*>(row1 + c + 8);
            s0 += a00.x*a00.x + a00.y*a00.y + a01.x*a01.x + a01.y*a01.y;
            s1 += a10.x*a10.x + a10.y*a10.y + a11.x*a11.x + a11.y*a11.y;
            uint4 o;
            o.x = pack_bf16x2(a00.x, a00.y);
            o.y = pack_bf16x2(a10.x, a10.y);
            o.z = pack_bf16x2(a01.x, a01.y);
            o.w = pack_bf16x2(a11.x, a11.y);
            dst[kb * 32 + lane] = o;
        }
        s0 += __shfl_xor_sync(0xffffffffu, s0, 1);
        s0 += __shfl_xor_sync(0xffffffffu, s0, 2);
        s1 += __shfl_xor_sync(0xffffffffu, s1, 1);
        s1 += __shfl_xor_sync(0xffffffffu, s1, 2);
        if ((lane & 3) == 0) {
            g_xsq[r0]     = s0;
            g_xsq[r0 + 8] = s1;
        }
    } else {
        const int r = wid - NMB;
        if (r >= Ndim) return;
        const float4* src = reinterpret_cast<const float4*>(cb)
                          + (size_t)r * (Kdim / 4);
        __nv_bfloat16* dstb = g_cb + (size_t)r * Kdim;
        float s = 0.f;
        #pragma unroll
        for (int t = 0; t < Kdim / 128; t++) {
            int j = lane + t * 32;
            float4 v = src[j];
            s += v.x * v.x + v.y * v.y + v.z * v.z + v.w * v.w;
            uint2 pk;
            pk.x = pack_bf16x2(v.x, v.y);
            pk.y = pack_bf16x2(v.z, v.w);
            *reinterpret_cast<uint2*>(dstb + j * 4) = pk;
        }
        #pragma unroll
        for (int o = 16; o; o >>= 1) s += __shfl_xor_sync(0xffffffffu, s, o);
        if (lane == 0) g_csq[r] = s;
    }
}

// ------- B chunk loader: 128 rows x 64 bf16 (128B), SW128 -------
__device__ __forceinline__ void load_chunkB(int n0, int c, uint32_t stg, int tid) {
    const __nv_bfloat16* cbp = g_cb + (size_t)n0 * Kdim + c * KC;
    #pragma unroll
    for (int t = 0; t < 8; t++) {
        int i  = tid + t * THREADS;   // 0..1023
        int r  = i >> 3;              // row 0..127
        int j4 = i & 7;
        uint32_t off = SW128((uint32_t)(r * 128 + j4 * 16));
        cp16(stg + off, cbp + (size_t)r * Kdim + j4 * 8);
    }
}

// ---------------- GEMM: B via smem, A via LDG fragment records ------------
__global__ void __launch_bounds__(THREADS, 4)
gemm_kernel(const float* __restrict__ precision, float* __restrict__ out) {
    extern __shared__ char smem[];
    const uint32_t sb = smem_u32(smem);
    const int tid  = threadIdx.x;
    const int lane = tid & 31;
    const int w    = tid >> 5;
    const int wm   = w >> 1;          // 0..1
    const int wn   = w & 1;           // 0..1
    const int m0 = blockIdx.y * MT;
    const int n0 = blockIdx.x * NT;

    // B ldmatrix offsets (bytes within 128B-row stage, pre-swizzle)
    const int bRow0 = wn * 64 + (lane & 7) + ((lane >> 4) & 1) * 8;
    const int bColB = ((lane >> 3) & 1) * 16;

    // A record indices (uint4 units): warp wm owns m-blocks mb0, mb0+1
    const int mb0 = blockIdx.y * 4 + wm * 2;
    uint32_t iA[2];
    #pragma unroll
    for (int mf = 0; mf < 2; mf++)
        iA[mf] = ((uint32_t)(mb0 + mf) * NKB) * 32 + lane;

    float acc[2][8][4];
    #pragma unroll
    for (int mf = 0; mf < 2; mf++)
        #pragma unroll
        for (int nf = 0; nf < 8; nf++)
            #pragma unroll
            for (int q = 0; q < 4; q++) acc[mf][nf][q] = 0.f;

    // prologue: B chunk 0 in flight; A kb=0 fragments in regs
    load_chunkB(n0, 0, sb, tid); CP_COMMIT();
    uint4 Ab[2][2];
    #pragma unroll
    for (int mf = 0; mf < 2; mf++) Ab[0][mf] = g_af[iA[mf]];

    #pragma unroll 1
    for (int c = 0; c < NCHUNK; c++) {
        CP_WAIT(0);
        __syncthreads();      // B chunk c visible; other stage free
        if (c + 1 < NCHUNK) {
            load_chunkB(n0, c + 1, sb + ((c + 1) & 1) * STAGE_BYTES, tid);
            CP_COMMIT();
        }
        const uint32_t sB = sb + (c & 1) * STAGE_BYTES;
        #pragma unroll
        for (int ks = 0; ks < 4; ks++) {            // k16 steps
            const int kb = c * 4 + ks;
            const int cur = kb & 1, nxt = cur ^ 1;
            if (kb + 1 < NKB) {                     // prefetch next A frags
                #pragma unroll
                for (int mf = 0; mf < 2; mf++)
                    Ab[nxt][mf] = g_af[iA[mf] + (uint32_t)(kb + 1) * 32];
            }
            uint32_t bf[4][4];
            #pragma unroll
            for (int nf2 = 0; nf2 < 4; nf2++)
                ldsm_x4(bf[nf2], sB + SW128((uint32_t)((bRow0 + nf2 * 16) * 128
                                                       + ks * 32 + bColB)));
            #pragma unroll
            for (int mf = 0; mf < 2; mf++) {
                const uint32_t* a = reinterpret_cast<const uint32_t*>(&Ab[cur][mf]);
                #pragma unroll
                for (int nf = 0; nf < 8; nf++)
                    mma_bf16(acc[mf][nf], a,
                             bf[nf >> 1][(nf & 1) * 2],
                             bf[nf >> 1][(nf & 1) * 2 + 1]);
            }
        }
        __syncthreads();      // all warps done reading stage c
    }

    // ---------------- epilogue ----------------
    float* sE = reinterpret_cast<float*>(smem);   // [64][132] = 33.8 KB
    const int erow = wm * 32 + (lane >> 2);
    const int ecol = wn * 64 + (lane & 3) * 2;
    #pragma unroll
    for (int mf = 0; mf < 2; mf++) {
        #pragma unroll
        for (int nf = 0; nf < 8; nf++) {
            float2* p0 = reinterpret_cast<float2*>(
                &sE[(erow + mf * 16) * 132 + ecol + nf * 8]);
            float2* p1 = reinterpret_cast<float2*>(
                &sE[(erow + mf * 16 + 8) * 132 + ecol + nf * 8]);
            *p0 = make_float2(acc[mf][nf][0], acc[mf][nf][1]);
            *p1 = make_float2(acc[mf][nf][2], acc[mf][nf][3]);
        }
    }
    __syncthreads();

    const float prec = precision[0];
    const int cj = (tid & 31) * 4;              // col group of 4 (128 cols)
    const float4 cs = *reinterpret_cast<const float4*>(&g_csq[n0 + cj]);
    #pragma unroll 4
    for (int it = 0; it < 16; it++) {
        const int r = (tid >> 5) + it * 4;      // 0..63
        const float xs = g_xsq[m0 + r];
        const float* sp = &sE[r * 132 + cj];
        float4 v;
        v.x = prec * (2.f * sp[0] - xs - cs.x);
        v.y = prec * (2.f * sp[1] - xs - cs.y);
        v.z = prec * (2.f * sp[2] - xs - cs.z);
        v.w = prec * (2.f * sp[3] - xs - cs.w);
        *reinterpret_cast<float4*>(&out[(size_t)(m0 + r) * Ndim + n0 + cj]) = v;
    }
}

// ---------------- launch ----------------
extern "C" void kernel_launch(void* const* d_in, const int* in_sizes, int n_in,
                              void* d_out, int out_size) {
    (void)in_sizes; (void)n_in; (void)out_size;
    const float* x    = (const float*)d_in[0];
    const float* cb   = (const float*)d_in[1];
    const float* prec = (const float*)d_in[2];
    float* out = (float*)d_out;

    cudaFuncSetAttribute(gemm_kernel,
                         cudaFuncAttributeMaxDynamicSharedMemorySize, SM_TOTAL);

    prep_kernel<<<(NMB + Ndim + 7) / 8, 256>>>(x, cb);
    dim3 grid(Ndim / NT, Mdim / MT);   // (8, 128) = 1024 CTAs
    gemm_kernel<<<grid, THREADS, SM_TOTAL>>>(prec, out);
}

// round 15
// speedup vs baseline: 1.1811x; 1.1811x over previous
#include <cuda_runtime.h>
#include <cuda_bf16.h>
#include <cstdint>
#include <cstddef>

// ---------------- problem dims ----------------
static constexpr int Mdim = 8192;   // B*T
static constexpr int Ndim = 1024;   // codebook rows
static constexpr int Kdim = 512;    // D

// ---------------- tiling: 64x128 CTA, 4 barrier domains/SM ----------------
static constexpr int MT = 64;
static constexpr int NT = 128;
static constexpr int KC = 64;            // K elems per chunk (64 bf16 = 128B rows)
static constexpr int NCHUNK = Kdim / KC; // 8
static constexpr int THREADS = 128;      // 4 warps: 2 (M) x 2 (N), 32x64 each
static constexpr int STAGES = 2;
static constexpr int STAGE_BYTES = 24576;             // A 8K | B 16K
static constexpr int SM_TOTAL = STAGES * STAGE_BYTES; // 48 KB -> 4 CTAs/SM

__device__ float g_xsq[Mdim];
__device__ float g_csq[Ndim];
__device__ __nv_bfloat16 g_xb[(size_t)Mdim * Kdim];   // 8 MB
__device__ __nv_bfloat16 g_cb[(size_t)Ndim * Kdim];   // 1 MB

// ---------------- helpers ----------------
__device__ __forceinline__ uint32_t smem_u32(const void* p) {
    uint32_t a;
    asm("{ .reg .u64 t; cvta.to.shared.u64 t, %1; cvt.u32.u64 %0, t; }"
        : "=r"(a) : "l"(p));
    return a;
}
#define SW128(o) ((o) ^ (((o) >> 3) & 0x70))

__device__ __forceinline__ uint32_t pack_bf16x2(float a, float b) {
    uint32_t r;
    asm("cvt.rn.bf16x2.f32 %0, %1, %2;" : "=r"(r) : "f"(b), "f"(a));
    return r;
}
__device__ __forceinline__ void cp16(uint32_t dst, const void* src) {
    asm volatile("cp.async.cg.shared.global [%0], [%1], 16;"
                 :: "r"(dst), "l"(src) : "memory");
}
#define CP_COMMIT() asm volatile("cp.async.commit_group;" ::: "memory")
#define CP_WAIT(n)  asm volatile("cp.async.wait_group %0;" :: "n"(n) : "memory")

__device__ __forceinline__ void ldsm_x4(uint32_t* r, uint32_t addr) {
    asm volatile("ldmatrix.sync.aligned.m8n8.x4.shared.b16 {%0,%1,%2,%3}, [%4];"
                 : "=r"(r[0]), "=r"(r[1]), "=r"(r[2]), "=r"(r[3]) : "r"(addr));
}
__device__ __forceinline__ void mma_bf16(float* c, const uint32_t* a,
                                         uint32_t b0, uint32_t b1) {
    asm volatile(
        "mma.sync.aligned.m16n8k16.row.col.f32.bf16.bf16.f32 "
        "{%0,%1,%2,%3}, {%4,%5,%6,%7}, {%8,%9}, {%0,%1,%2,%3};"
        : "+f"(c[0]), "+f"(c[1]), "+f"(c[2]), "+f"(c[3])
        : "r"(a[0]), "r"(a[1]), "r"(a[2]), "r"(a[3]), "r"(b0), "r"(b1));
}

// ------- prep: fp32 -> bf16 + row norms, one read pass (R5-proven) -------
__global__ void __launch_bounds__(256) prep_kernel(const float* __restrict__ x,
                                                   const float* __restrict__ cb) {
    int row  = blockIdx.x * 8 + (threadIdx.x >> 5);
    int lane = threadIdx.x & 31;
    const float4* src;
    __nv_bfloat16* dstb;
    float* dsts;
    if (row < Mdim) {
        src  = reinterpret_cast<const float4*>(x) + (size_t)row * (Kdim / 4);
        dstb = g_xb + (size_t)row * Kdim;
        dsts = g_xsq + row;
    } else if (row < Mdim + Ndim) {
        int r = row - Mdim;
        src  = reinterpret_cast<const float4*>(cb) + (size_t)r * (Kdim / 4);
        dstb = g_cb + (size_t)r * Kdim;
        dsts = g_csq + r;
    } else return;
    float s = 0.f;
    #pragma unroll
    for (int t = 0; t < Kdim / 128; t++) {
        int j = lane + t * 32;
        float4 v = src[j];
        s += v.x * v.x + v.y * v.y + v.z * v.z + v.w * v.w;
        uint2 pk;
        pk.x = pack_bf16x2(v.x, v.y);
        pk.y = pack_bf16x2(v.z, v.w);
        *reinterpret_cast<uint2*>(dstb + j * 4) = pk;
    }
    #pragma unroll
    for (int o = 16; o; o >>= 1) s += __shfl_xor_sync(0xffffffffu, s, o);
    if (lane == 0) *dsts = s;
}

// ------- chunk loader: 64x64bf16 A + 128x64bf16 B, SW128 -------
__device__ __forceinline__ void load_chunk(int m0, int n0, int c,
                                           uint32_t stg, int tid) {
    const __nv_bfloat16* xa  = g_xb + (size_t)m0 * Kdim + c * KC;
    const __nv_bfloat16* cbp = g_cb + (size_t)n0 * Kdim + c * KC;
    // A: 64 rows x 128B = 512 cp16
    #pragma unroll
    for (int t = 0; t < 4; t++) {
        int i  = tid + t * THREADS;   // 0..511
        int r  = i >> 3;              // row 0..63
        int j4 = i & 7;
        uint32_t off = SW128((uint32_t)(r * 128 + j4 * 16));
        cp16(stg + off, xa + (size_t)r * Kdim + j4 * 8);
    }
    // B: 128 rows x 128B = 1024 cp16, at +8KB
    #pragma unroll
    for (int t = 0; t < 8; t++) {
        int i  = tid + t * THREADS;   // 0..1023
        int r  = i >> 3;              // row 0..127
        int j4 = i & 7;
        uint32_t off = SW128((uint32_t)(r * 128 + j4 * 16));
        cp16(stg + 8192u + off, cbp + (size_t)r * Kdim + j4 * 8);
    }
}

// ---------------- GEMM + fused epilogue ----------------
__global__ void __launch_bounds__(THREADS, 4)
gemm_kernel(const float* __restrict__ precision, float* __restrict__ out) {
    extern __shared__ char smem[];
    const uint32_t sb = smem_u32(smem);
    const int tid  = threadIdx.x;
    const int lane = tid & 31;
    const int w    = tid >> 5;
    const int wm   = w >> 1;          // 0..1
    const int wn   = w & 1;           // 0..1
    const int m0 = blockIdx.y * MT;
    const int n0 = blockIdx.x * NT;

    // ldmatrix per-thread offsets (bytes within 128B-row tiles, pre-swizzle)
    const int aRow0 = wm * 32 + (lane & 15);
    const int aColB = ((lane >> 4) & 1) * 16;
    const int bRow0 = wn * 64 + (lane & 7) + ((lane >> 4) & 1) * 8;
    const int bColB = ((lane >> 3) & 1) * 16;

    float acc[2][8][4];
    #pragma unroll
    for (int mf = 0; mf < 2; mf++)
        #pragma unroll
        for (int nf = 0; nf < 8; nf++)
            #pragma unroll
            for (int q = 0; q < 4; q++) acc[mf][nf][q] = 0.f;

    // prologue: chunk 0 in flight
    load_chunk(m0, n0, 0, sb, tid); CP_COMMIT();

    #pragma unroll 1
    for (int c = 0; c < NCHUNK; c++) {
        CP_WAIT(0);
        __syncthreads();      // chunk c visible to all warps; old stage free
        if (c + 1 < NCHUNK) {
            load_chunk(m0, n0, c + 1, sb + ((c + 1) & 1) * STAGE_BYTES, tid);
            CP_COMMIT();
        }
        const uint32_t sA = sb + (c & 1) * STAGE_BYTES;
        const uint32_t sB = sA + 8192u;

        // B fragments double-buffered; A just-in-time (2 LDSM)
        uint32_t bf[2][4][4];
        #pragma unroll
        for (int nf2 = 0; nf2 < 4; nf2++)
            ldsm_x4(bf[0][nf2], sB + SW128((uint32_t)((bRow0 + nf2 * 16) * 128
                                                      + bColB)));
        #pragma unroll
        for (int ks = 0; ks < 4; ks++) {
            const int cur = ks & 1, nxt = cur ^ 1;
            if (ks < 3) {     // prefetch next k-step's B fragments
                #pragma unroll
                for (int nf2 = 0; nf2 < 4; nf2++)
                    ldsm_x4(bf[nxt][nf2],
                            sB + SW128((uint32_t)((bRow0 + nf2 * 16) * 128
                                                  + (ks + 1) * 32 + bColB)));
            }
            uint32_t af[2][4];
            #pragma unroll
            for (int mf = 0; mf < 2; mf++)
                ldsm_x4(af[mf], sA + SW128((uint32_t)((aRow0 + mf * 16) * 128
                                                      + ks * 32 + aColB)));
            #pragma unroll
            for (int mf = 0; mf < 2; mf++)
                #pragma unroll
                for (int nf = 0; nf < 8; nf++)
                    mma_bf16(acc[mf][nf], af[mf],
                             bf[cur][nf >> 1][(nf & 1) * 2],
                             bf[cur][nf >> 1][(nf & 1) * 2 + 1]);
        }
        __syncthreads();      // all warps done with stage c before next refill
    }

    // ---------------- epilogue ----------------
    float* sE = reinterpret_cast<float*>(smem);   // [64][132] = 33.8 KB
    const int erow = wm * 32 + (lane >> 2);
    const int ecol = wn * 64 + (lane & 3) * 2;
    #pragma unroll
    for (int mf = 0; mf < 2; mf++) {
        #pragma unroll
        for (int nf = 0; nf < 8; nf++) {
            float2* p0 = reinterpret_cast<float2*>(
                &sE[(erow + mf * 16) * 132 + ecol + nf * 8]);
            float2* p1 = reinterpret_cast<float2*>(
                &sE[(erow + mf * 16 + 8) * 132 + ecol + nf * 8]);
            *p0 = make_float2(acc[mf][nf][0], acc[mf][nf][1]);
            *p1 = make_float2(acc[mf][nf][2], acc[mf][nf][3]);
        }
    }
    __syncthreads();

    const float prec = precision[0];
    const int cj = (tid & 31) * 4;              // col group of 4 (128 cols)
    const float4 cs = *reinterpret_cast<const float4*>(&g_csq[n0 + cj]);
    #pragma unroll 4
    for (int it = 0; it < 16; it++) {
        const int r = (tid >> 5) + it * 4;      // 0..63
        const float xs = g_xsq[m0 + r];
        const float* sp = &sE[r * 132 + cj];
        float4 v;
        v.x = prec * (2.f * sp[0] - xs - cs.x);
        v.y = prec * (2.f * sp[1] - xs - cs.y);
        v.z = prec * (2.f * sp[2] - xs - cs.z);
        v.w = prec * (2.f * sp[3] - xs - cs.w);
        *reinterpret_cast<float4*>(&out[(size_t)(m0 + r) * Ndim + n0 + cj]) = v;
    }
}

// ---------------- launch ----------------
extern "C" void kernel_launch(void* const* d_in, const int* in_sizes, int n_in,
                              void* d_out, int out_size) {
    (void)in_sizes; (void)n_in; (void)out_size;
    const float* x    = (const float*)d_in[0];
    const float* cb   = (const float*)d_in[1];
    const float* prec = (const float*)d_in[2];
    float* out = (float*)d_out;

    cudaFuncSetAttribute(gemm_kernel,
                         cudaFuncAttributeMaxDynamicSharedMemorySize, SM_TOTAL);

    prep_kernel<<<(Mdim + Ndim) / 8, 256>>>(x, cb);
    dim3 grid(Ndim / NT, Mdim / MT);   // (8, 128) = 1024 CTAs
    gemm_kernel<<<grid, THREADS, SM_TOTAL>>>(prec, out);
}

// round 16
// speedup vs baseline: 1.1834x; 1.0019x over previous
#include <cuda_runtime.h>
#include <cuda_bf16.h>
#include <cstdint>
#include <cstddef>

// ---------------- problem dims ----------------
static constexpr int Mdim = 8192;   // B*T
static constexpr int Ndim = 1024;   // codebook rows
static constexpr int Kdim = 512;    // D

// ---------------- tiling: 64x128 CTA, 4 barrier domains/SM ----------------
static constexpr int MT = 64;
static constexpr int NT = 128;
static constexpr int KC = 64;            // K elems per chunk
static constexpr int NCHUNK = Kdim / KC; // 8
static constexpr int THREADS = 128;      // 4 warps: 2 (M) x 2 (N), 32x64 each
static constexpr int A_CHUNK_BYTES = 64 * 128;    // 8 KB  (64 rows x 128B)
static constexpr int B_CHUNK_BYTES = 128 * 128;   // 16 KB (128 rows x 128B)
static constexpr int STAGE_BYTES = A_CHUNK_BYTES + B_CHUNK_BYTES; // 24576
static constexpr int SM_MBAR = 2 * STAGE_BYTES;   // 49152
static constexpr int SM_TOTAL = SM_MBAR + 64;     // 49216 -> 4 CTAs/SM

__device__ float g_xsq[Mdim];
__device__ float g_csq[Ndim];
// chunk-blocked, PRE-SWIZZLED bf16 images: one contiguous block per (tile, chunk)
__device__ __align__(16) uint8_t g_xb[(size_t)(Mdim / 64) * NCHUNK * A_CHUNK_BYTES];  // 8 MB
__device__ __align__(16) uint8_t g_cb[(size_t)(Ndim / 128) * NCHUNK * B_CHUNK_BYTES]; // 1 MB

// ---------------- helpers ----------------
__device__ __forceinline__ uint32_t smem_u32(const void* p) {
    uint32_t a;
    asm("{ .reg .u64 t; cvta.to.shared.u64 t, %1; cvt.u32.u64 %0, t; }"
        : "=r"(a) : "l"(p));
    return a;
}
#define SW128(o) ((o) ^ (((o) >> 3) & 0x70))

__device__ __forceinline__ uint32_t pack_bf16x2(float a, float b) {
    uint32_t r;
    asm("cvt.rn.bf16x2.f32 %0, %1, %2;" : "=r"(r) : "f"(b), "f"(a));
    return r;
}
__device__ __forceinline__ void ldsm_x4(uint32_t* r, uint32_t addr) {
    asm volatile("ldmatrix.sync.aligned.m8n8.x4.shared.b16 {%0,%1,%2,%3}, [%4];"
                 : "=r"(r[0]), "=r"(r[1]), "=r"(r[2]), "=r"(r[3]) : "r"(addr));
}
__device__ __forceinline__ void mma_bf16(float* c, const uint32_t* a,
                                         uint32_t b0, uint32_t b1) {
    asm volatile(
        "mma.sync.aligned.m16n8k16.row.col.f32.bf16.bf16.f32 "
        "{%0,%1,%2,%3}, {%4,%5,%6,%7}, {%8,%9}, {%0,%1,%2,%3};"
        : "+f"(c[0]), "+f"(c[1]), "+f"(c[2]), "+f"(c[3])
        : "r"(a[0]), "r"(a[1]), "r"(a[2]), "r"(a[3]), "r"(b0), "r"(b1));
}

#define MBAR_INIT(a, cnt) \
    asm volatile("mbarrier.init.shared.b64 [%0], %1;" :: "r"(a), "r"(cnt) : "memory")
#define MBAR_EXPECT_TX(a, bytes) \
    asm volatile("mbarrier.arrive.expect_tx.shared.b64 _, [%0], %1;" \
                 :: "r"(a), "r"(bytes) : "memory")
#define MBAR_WAIT(addr, ph) do {                                                    \
    asm volatile(                                                                   \
        "{\n\t.reg .pred P;\n"                                                      \
        "MW_%=:\n\t"                                                                \
        "mbarrier.try_wait.parity.acquire.cta.shared::cta.b64 P, [%0], %1, 0x989680;\n\t" \
        "@P bra.uni MD_%=;\n\t"                                                     \
        "bra.uni MW_%=;\n"                                                          \
        "MD_%=:\n\t}"                                                               \
        :: "r"(addr), "r"(ph) : "memory");                                          \
} while (0)

__device__ __forceinline__ void bulk_copy(uint32_t dst_smem, const void* src,
                                          uint32_t bytes, uint32_t mbar) {
    asm volatile(
        "cp.async.bulk.shared::cluster.global.mbarrier::complete_tx::bytes "
        "[%0], [%1], %2, [%3];"
        :: "r"(dst_smem), "l"(src), "r"(bytes), "r"(mbar) : "memory");
}

// ------- prep: fp32 -> bf16 into chunk-blocked PRE-SWIZZLED layout + norms --
// One warp per row. Lane l, iter t: j = l + t*32 (float4 index; k = 4j).
// chunk = j>>4; in-chunk byte = (j&15)*8; swizzled within the 128B row.
__global__ void __launch_bounds__(256) prep_kernel(const float* __restrict__ x,
                                                   const float* __restrict__ cb) {
    int row  = blockIdx.x * 8 + (threadIdx.x >> 5);
    int lane = threadIdx.x & 31;
    const float4* src;
    uint8_t* dstbase;
    float* dsts;
    int rloc, cbytes;
    if (row < Mdim) {
        src = reinterpret_cast<const float4*>(x) + (size_t)row * (Kdim / 4);
        dstbase = g_xb + (size_t)(row >> 6) * NCHUNK * A_CHUNK_BYTES;
        rloc = row & 63;  cbytes = A_CHUNK_BYTES;
        dsts = g_xsq + row;
    } else if (row < Mdim + Ndim) {
        int r = row - Mdim;
        src = reinterpret_cast<const float4*>(cb) + (size_t)r * (Kdim / 4);
        dstbase = g_cb + (size_t)(r >> 7) * NCHUNK * B_CHUNK_BYTES;
        rloc = r & 127;  cbytes = B_CHUNK_BYTES;
        dsts = g_csq + r;
    } else return;
    float s = 0.f;
    #pragma unroll
    for (int t = 0; t < Kdim / 128; t++) {
        int j = lane + t * 32;
        float4 v = src[j];
        s += v.x * v.x + v.y * v.y + v.z * v.z + v.w * v.w;
        uint2 pk;
        pk.x = pack_bf16x2(v.x, v.y);
        pk.y = pack_bf16x2(v.z, v.w);
        const int c = j >> 4;
        const uint32_t off = SW128((uint32_t)(rloc * 128 + (j & 15) * 8));
        *reinterpret_cast<uint2*>(dstbase + (size_t)c * cbytes + off) = pk;
    }
    #pragma unroll
    for (int o = 16; o; o >>= 1) s += __shfl_xor_sync(0xffffffffu, s, o);
    if (lane == 0) *dsts = s;
}

// ---------------- GEMM: bulk-copy fed stages, no LDGSTS/STS ----------------
__global__ void __launch_bounds__(THREADS, 4)
gemm_kernel(const float* __restrict__ precision, float* __restrict__ out) {
    extern __shared__ char smem[];
    const uint32_t sb = smem_u32(smem);
    const int tid  = threadIdx.x;
    const int lane = tid & 31;
    const int w    = tid >> 5;
    const int wm   = w >> 1;          // 0..1
    const int wn   = w & 1;           // 0..1
    const int m0 = blockIdx.y * MT;
    const int n0 = blockIdx.x * NT;
    const uint8_t* srcA = g_xb + (size_t)blockIdx.y * NCHUNK * A_CHUNK_BYTES;
    const uint8_t* srcB = g_cb + (size_t)blockIdx.x * NCHUNK * B_CHUNK_BYTES;

    // ldmatrix per-thread offsets (bytes within 128B-row tiles, pre-swizzle)
    const int aRow0 = wm * 32 + (lane & 15);
    const int aColB = ((lane >> 4) & 1) * 16;
    const int bRow0 = wn * 64 + (lane & 7) + ((lane >> 4) & 1) * 8;
    const int bColB = ((lane >> 3) & 1) * 16;

    float acc[2][8][4];
    #pragma unroll
    for (int mf = 0; mf < 2; mf++)
        #pragma unroll
        for (int nf = 0; nf < 8; nf++)
            #pragma unroll
            for (int q = 0; q < 4; q++) acc[mf][nf][q] = 0.f;

    // mbarrier setup (one per stage)
    if (tid == 0) {
        MBAR_INIT(sb + SM_MBAR + 0, 1);
        MBAR_INIT(sb + SM_MBAR + 8, 1);
    }
    asm volatile("fence.proxy.async.shared::cta;" ::: "memory");
    __syncthreads();

    // prologue: issue chunk 0
    if (tid == 0) {
        MBAR_EXPECT_TX(sb + SM_MBAR + 0, (uint32_t)STAGE_BYTES);
        bulk_copy(sb, srcA, A_CHUNK_BYTES, sb + SM_MBAR + 0);
        bulk_copy(sb + A_CHUNK_BYTES, srcB + 0, B_CHUNK_BYTES, sb + SM_MBAR + 0);
    }

    #pragma unroll 1
    for (int c = 0; c < NCHUNK; c++) {
        if (c >= 1) __syncthreads();   // all warps done reading chunk c-1
        if (c + 1 < NCHUNK && tid == 0) {
            const int s2 = (c + 1) & 1;
            MBAR_EXPECT_TX(sb + SM_MBAR + 8 * s2, (uint32_t)STAGE_BYTES);
            bulk_copy(sb + s2 * STAGE_BYTES,
                      srcA + (size_t)(c + 1) * A_CHUNK_BYTES,
                      A_CHUNK_BYTES, sb + SM_MBAR + 8 * s2);
            bulk_copy(sb + s2 * STAGE_BYTES + A_CHUNK_BYTES,
                      srcB + (size_t)(c + 1) * B_CHUNK_BYTES,
                      B_CHUNK_BYTES, sb + SM_MBAR + 8 * s2);
        }
        MBAR_WAIT(sb + SM_MBAR + 8 * (c & 1), (c >> 1) & 1);

        const uint32_t sA = sb + (c & 1) * STAGE_BYTES;
        const uint32_t sB = sA + A_CHUNK_BYTES;

        // B fragments double-buffered; A just-in-time (R15-proven schedule)
        uint32_t bf[2][4][4];
        #pragma unroll
        for (int nf2 = 0; nf2 < 4; nf2++)
            ldsm_x4(bf[0][nf2], sB + SW128((uint32_t)((bRow0 + nf2 * 16) * 128
                                                      + bColB)));
        #pragma unroll
        for (int ks = 0; ks < 4; ks++) {
            const int cur = ks & 1, nxt = cur ^ 1;
            if (ks < 3) {
                #pragma unroll
                for (int nf2 = 0; nf2 < 4; nf2++)
                    ldsm_x4(bf[nxt][nf2],
                            sB + SW128((uint32_t)((bRow0 + nf2 * 16) * 128
                                                  + (ks + 1) * 32 + bColB)));
            }
            uint32_t af[2][4];
            #pragma unroll
            for (int mf = 0; mf < 2; mf++)
                ldsm_x4(af[mf], sA + SW128((uint32_t)((aRow0 + mf * 16) * 128
                                                      + ks * 32 + aColB)));
            #pragma unroll
            for (int mf = 0; mf < 2; mf++)
                #pragma unroll
                for (int nf = 0; nf < 8; nf++)
                    mma_bf16(acc[mf][nf], af[mf],
                             bf[cur][nf >> 1][(nf & 1) * 2],
                             bf[cur][nf >> 1][(nf & 1) * 2 + 1]);
        }
    }
    __syncthreads();   // all warps done with stage smem before epilogue reuse

    // ---------------- epilogue ----------------
    float* sE = reinterpret_cast<float*>(smem);   // [64][132] = 33.8 KB
    const int erow = wm * 32 + (lane >> 2);
    const int ecol = wn * 64 + (lane & 3) * 2;
    #pragma unroll
    for (int mf = 0; mf < 2; mf++) {
        #pragma unroll
        for (int nf = 0; nf < 8; nf++) {
            float2* p0 = reinterpret_cast<float2*>(
                &sE[(erow + mf * 16) * 132 + ecol + nf * 8]);
            float2* p1 = reinterpret_cast<float2*>(
                &sE[(erow + mf * 16 + 8) * 132 + ecol + nf * 8]);
            *p0 = make_float2(acc[mf][nf][0], acc[mf][nf][1]);
            *p1 = make_float2(acc[mf][nf][2], acc[mf][nf][3]);
        }
    }
    __syncthreads();

    const float prec = precision[0];
    const int cj = (tid & 31) * 4;              // col group of 4 (128 cols)
    const float4 cs = *reinterpret_cast<const float4*>(&g_csq[n0 + cj]);
    #pragma unroll 4
    for (int it = 0; it < 16; it++) {
        const int r = (tid >> 5) + it * 4;      // 0..63
        const float xs = g_xsq[m0 + r];
        const float* sp = &sE[r * 132 + cj];
        float4 v;
        v.x = prec * (2.f * sp[0] - xs - cs.x);
        v.y = prec * (2.f * sp[1] - xs - cs.y);
        v.z = prec * (2.f * sp[2] - xs - cs.z);
        v.w = prec * (2.f * sp[3] - xs - cs.w);
        *reinterpret_cast<float4*>(&out[(size_t)(m0 + r) * Ndim + n0 + cj]) = v;
    }
}

// ---------------- launch ----------------
extern "C" void kernel_launch(void* const* d_in, const int* in_sizes, int n_in,
                              void* d_out, int out_size) {
    (void)in_sizes; (void)n_in; (void)out_size;
    const float* x    = (const float*)d_in[0];
    const float* cb   = (const float*)d_in[1];
    const float* prec = (const float*)d_in[2];
    float* out = (float*)d_out;

    cudaFuncSetAttribute(gemm_kernel,
                         cudaFuncAttributeMaxDynamicSharedMemorySize, SM_TOTAL);

    prep_kernel<<<(Mdim + Ndim) / 8, 256>>>(x, cb);
    dim3 grid(Ndim / NT, Mdim / MT);   // (8, 128) = 1024 CTAs
    gemm_kernel<<<grid, THREADS, SM_TOTAL>>>(prec, out);
}